// round 14
// baseline (speedup 1.0000x reference)
#include <cuda_runtime.h>

#define NB 256
#define NT 1024
#define NI 64
#define NH 25
#define NG 100    // real gate columns
#define NGP 104   // padded gate stride (13*8)
#define NO 64
#define NM (NB*NT)  // 262144 rows

// Precomputed input gates, layout [row][k*4+{i,f,g,o}] padded to 104: ~109 MB
static __device__ float g_gates[(size_t)NM * NGP];
// Precomputed W_ih fragments: [kstg 0..7][n 0..103][qid 0..3] = {bh0,bh1,bl0,bl1}
static __device__ uint4 g_wq[8 * NGP * 4];
static __device__ float g_bsum[NGP];

typedef unsigned long long ull;
typedef unsigned int uint;

__device__ __forceinline__ ull pack2(float a, float b){
    ull r; asm("mov.b64 %0,{%1,%2};" : "=l"(r) : "f"(a), "f"(b)); return r;
}
__device__ __forceinline__ float2 unpack2(ull v){
    float2 r; asm("mov.b64 {%0,%1},%2;" : "=f"(r.x), "=f"(r.y) : "l"(v)); return r;
}
__device__ __forceinline__ ull fma2(ull a, ull b, ull c){
    ull d; asm("fma.rn.f32x2 %0,%1,%2,%3;" : "=l"(d) : "l"(a), "l"(b), "l"(c)); return d;
}
__device__ __forceinline__ ull add2(ull a, ull b){
    ull d; asm("add.rn.f32x2 %0,%1,%2;" : "=l"(d) : "l"(a), "l"(b)); return d;
}
__device__ __forceinline__ float tanha(float x){
    float r; asm("tanh.approx.f32 %0,%1;" : "=f"(r) : "f"(x)); return r;
}
__device__ __forceinline__ float sig_t(float x){
    return fmaf(tanha(0.5f * x), 0.5f, 0.5f);
}
__device__ __forceinline__ unsigned smem_u32(const void* p){
    unsigned a;
    asm("{ .reg .u64 t; cvta.to.shared.u64 t, %1; cvt.u32.u64 %0, t; }"
        : "=r"(a) : "l"(p));
    return a;
}
__device__ __forceinline__ uint to_tf32(float v){
    uint r; asm("cvt.rna.tf32.f32 %0,%1;" : "=r"(r) : "f"(v)); return r;
}

#define MMA_TF32(c, a0,a1,a2,a3, b0,b1)                                   \
    asm volatile("mma.sync.aligned.m16n8k8.row.col.f32.tf32.tf32.f32 "    \
        "{%0,%1,%2,%3}, {%4,%5,%6,%7}, {%8,%9}, {%0,%1,%2,%3};"           \
        : "+f"((c)[0]), "+f"((c)[1]), "+f"((c)[2]), "+f"((c)[3])          \
        : "r"(a0), "r"(a1), "r"(a2), "r"(a3), "r"(b0), "r"(b1))

// ---------------------------------------------------------------------------
// Kernel 0: precompute W fragments + bias (R12 exact).
// ---------------------------------------------------------------------------
__global__ void prep_kernel(const float* __restrict__ W_ih,
                            const float* __restrict__ b_ih,
                            const float* __restrict__ b_hh)
{
    int tid = blockIdx.x * blockDim.x + threadIdx.x;
    const int total = 8 * NGP * 4;
    for (int i = tid; i < total; i += blockDim.x * gridDim.x){
        int qid  = i & 3;
        int n    = (i >> 2) % NGP;
        int kstg = i / (NGP * 4);
        int q = n & 3, kk = n >> 2;
        int k0 = kstg * 8 + qid, k1 = k0 + 4;
        float v0 = (kk < NH) ? W_ih[(q*NH + kk) * NI + k0] : 0.0f;
        float v1 = (kk < NH) ? W_ih[(q*NH + kk) * NI + k1] : 0.0f;
        uint h0 = to_tf32(v0), h1 = to_tf32(v1);
        uint l0 = to_tf32(v0 - __uint_as_float(h0));
        uint l1 = to_tf32(v1 - __uint_as_float(h1));
        g_wq[i] = make_uint4(h0, h1, l0, l1);
    }
    if (tid < NGP){
        int q = tid & 3, kk = tid >> 2;
        g_bsum[tid] = (kk < NH) ? (b_ih[q*NH + kk] + b_hh[q*NH + kk]) : 0.0f;
    }
}

// ---------------------------------------------------------------------------
// Kernel 1: gates via 3xTF32 tensor-core GEMM (R12 exact, b-major rows).
// ---------------------------------------------------------------------------
__global__ void __launch_bounds__(128) gates_kernel(const float* __restrict__ x)
{
    __shared__ uint  xs_hi[64][36], xs_lo[64][36];
    __shared__ uint4 bq[4][NGP][4];

    const int tid  = threadIdx.x;
    const int lane = tid & 31;
    const int wid  = tid >> 5;
    const int grp  = lane >> 2;
    const int qid  = lane & 3;
    const int rowbase = blockIdx.x * 64;

    float acc[13][4];
    #pragma unroll
    for (int nt = 0; nt < 13; nt++)
        #pragma unroll
        for (int i = 0; i < 4; i++) acc[nt][i] = 0.0f;

    const unsigned bq_s = smem_u32(&bq[0][0][0]);

    for (int pass = 0; pass < 2; pass++){
        const int ks = pass * 32;
        __syncthreads();

        {
            const char* src = reinterpret_cast<const char*>(g_wq)
                              + (size_t)pass * 4 * NGP * 4 * 16;
            #pragma unroll
            for (int i = 0; i < 13; i++){
                int off = (tid + i * 128) * 16;
                asm volatile("cp.async.ca.shared.global [%0], [%1], 16;"
                             :: "r"(bq_s + off), "l"(src + off) : "memory");
            }
            asm volatile("cp.async.commit_group;" ::: "memory");
        }

        #pragma unroll
        for (int i = 0; i < 4; i++){
            int idx = tid + i * 128;
            int r = idx >> 3, f4 = idx & 7;
            float4 v = *reinterpret_cast<const float4*>(
                x + (size_t)(rowbase + r) * NI + ks + f4 * 4);
            uint4 hb, lb;
            hb.x = to_tf32(v.x); lb.x = to_tf32(v.x - __uint_as_float(hb.x));
            hb.y = to_tf32(v.y); lb.y = to_tf32(v.y - __uint_as_float(hb.y));
            hb.z = to_tf32(v.z); lb.z = to_tf32(v.z - __uint_as_float(hb.z));
            hb.w = to_tf32(v.w); lb.w = to_tf32(v.w - __uint_as_float(hb.w));
            *reinterpret_cast<uint4*>(&xs_hi[r][f4 * 4]) = hb;
            *reinterpret_cast<uint4*>(&xs_lo[r][f4 * 4]) = lb;
        }
        asm volatile("cp.async.wait_group 0;" ::: "memory");
        __syncthreads();

        #pragma unroll
        for (int kst = 0; kst < 4; kst++){
            const int r0 = wid * 16 + grp;
            const int c0 = kst * 8 + qid;
            uint ah0 = xs_hi[r0][c0],   ah1 = xs_hi[r0+8][c0];
            uint ah2 = xs_hi[r0][c0+4], ah3 = xs_hi[r0+8][c0+4];
            uint al0 = xs_lo[r0][c0],   al1 = xs_lo[r0+8][c0];
            uint al2 = xs_lo[r0][c0+4], al3 = xs_lo[r0+8][c0+4];
            #pragma unroll
            for (int nt = 0; nt < 13; nt++){
                uint4 bv = bq[kst][nt * 8 + grp][qid];
                MMA_TF32(acc[nt], ah0, ah1, ah2, ah3, bv.x, bv.y);
                MMA_TF32(acc[nt], al0, al1, al2, al3, bv.x, bv.y);
                MMA_TF32(acc[nt], ah0, ah1, ah2, ah3, bv.z, bv.w);
            }
        }
    }

    const size_t rg = (size_t)(rowbase + wid * 16 + grp);
    #pragma unroll
    for (int nt = 0; nt < 13; nt++){
        int col = nt * 8 + 2 * qid;
        float2 bsv = *reinterpret_cast<const float2*>(&g_bsum[col]);
        float2 v0 = { acc[nt][0] + bsv.x, acc[nt][1] + bsv.y };
        float2 v1 = { acc[nt][2] + bsv.x, acc[nt][3] + bsv.y };
        *reinterpret_cast<float2*>(&g_gates[ rg      * NGP + col]) = v0;
        *reinterpret_cast<float2*>(&g_gates[(rg + 8) * NGP + col]) = v1;
    }
}

// ---------------------------------------------------------------------------
// Kernel 2: LSTM scan, 2 SCAN WARPS PER SMSP (latency-chain hiding).
// 64 blocks x 256 threads, 4 batches/block:
//   warps {0,1,4,5} = scan (SMSP 0,1 get two scan warps each)
//   warps {2,3,6,7} = FC helpers (SMSP 2,3, two each)
// Two interleaved scan warps fill each other's serial-chain bubbles.
// h via 16-slot smem ring, EP=8 epochs, 1 __syncthreads per epoch.
// gx via cp.async ring: 8 slots x 16B/lane, prefetch distance 6.
// ---------------------------------------------------------------------------
#define RD   8    // gx ring slots
#define RPD  6    // gx prefetch distance
#define EP   8    // steps per epoch
#define NEP  (NT/EP)   // 128 epochs

__global__ void __launch_bounds__(256, 1) lstm_kernel(
    const float* __restrict__ W_hh, const float* __restrict__ W_fc,
    const float* __restrict__ b_fc, float* __restrict__ out)
{
    __shared__ ull ring[4][RD][32][2];    // 16KB: gx ring per batch slot
    __shared__ ull hring[4][2*EP][32];    // 16KB: duplicated h pairs

    const int tid  = threadIdx.x;
    const int lane = tid & 31;
    const int wid  = tid >> 5;            // 0..7
    const int smsp = wid & 3;
    const int hi   = wid >> 2;            // 0,1
    const bool producer = (smsp < 2);
    const int bw   = producer ? (smsp + 2 * hi) : (smsp - 2 + 2 * hi);
    const int b    = blockIdx.x * 4 + bw;

    if (producer){
        // ---------------- producer: LSTM recurrence ----------------
        const int k = (lane < NH) ? lane : NH - 1;
        const float* gx = g_gates + (size_t)b * NT * NGP + 4 * k;

        ull w_if[NH], w_go[NH];
        #pragma unroll
        for (int kk = 0; kk < NH; kk++){
            w_if[kk] = pack2(__ldg(W_hh + (     k) * NH + kk), __ldg(W_hh + (NH  + k) * NH + kk));
            w_go[kk] = pack2(__ldg(W_hh + (2*NH+k) * NH + kk), __ldg(W_hh + (3*NH+k) * NH + kk));
        }

        const unsigned rbase = smem_u32(&ring[bw][0][lane][0]);
        #define SLOT_ADDR(s) (rbase + (unsigned)(s) * (32u * 16u))

        #pragma unroll
        for (int d = 0; d < RPD; d++){
            asm volatile("cp.async.ca.shared.global [%0], [%1], 16;"
                         :: "r"(SLOT_ADDR(d)), "l"(gx + (size_t)d * NGP) : "memory");
            asm volatile("cp.async.commit_group;" ::: "memory");
        }

        float h = 0.0f, c = 0.0f;

        for (int e = 0; e <= NEP; e++){
            if (e < NEP){
                #pragma unroll 4
                for (int u = 0; u < EP; u++){
                    const int t = e * EP + u;
                    asm volatile("cp.async.wait_group 5;" ::: "memory");
                    float4 pv = *reinterpret_cast<const float4*>(
                                    &ring[bw][t & (RD-1)][lane][0]);

                    {   // refill slot t+RPD
                        unsigned pred = (t + RPD < NT) ? 1u : 0u;
                        asm volatile(
                            "{ .reg .pred q; setp.ne.u32 q, %0, 0;"
                            "  @q cp.async.ca.shared.global [%1], [%2], 16; }"
                            :: "r"(pred), "r"(SLOT_ADDR((t + RPD) & (RD-1))),
                               "l"(gx + (size_t)(t + RPD) * NGP) : "memory");
                        asm volatile("cp.async.commit_group;" ::: "memory");
                    }

                    ull aif[4], ago[4];
                    aif[0] = pack2(pv.x, pv.y); aif[1] = 0ull; aif[2] = 0ull; aif[3] = 0ull;
                    ago[0] = pack2(pv.z, pv.w); ago[1] = 0ull; ago[2] = 0ull; ago[3] = 0ull;

                    #pragma unroll
                    for (int kk = 0; kk < NH; kk++){
                        float hv = __shfl_sync(0xffffffffu, h, kk);
                        ull hd = pack2(hv, hv);
                        aif[kk & 3] = fma2(hd, w_if[kk], aif[kk & 3]);
                        ago[kk & 3] = fma2(hd, w_go[kk], ago[kk & 3]);
                    }

                    float2 gif = unpack2(add2(add2(aif[0], aif[1]), add2(aif[2], aif[3])));
                    float2 ggo = unpack2(add2(add2(ago[0], ago[1]), add2(ago[2], ago[3])));
                    float iv = sig_t(gif.x);
                    float fv = sig_t(gif.y);
                    float gv = tanha(ggo.x);
                    float ov = sig_t(ggo.y);
                    c = fv * c + iv * gv;
                    h = ov * tanha(c);

                    hring[bw][t & (2*EP - 1)][lane] = pack2(h, h);
                }
            }
            __syncthreads();   // publish epoch e half; helpers drained e-1
        }
        #undef SLOT_ADDR
    } else {
        // ---------------- consumer: FC head ----------------
        const int o0 = 2 * lane;
        float* ob = out + (size_t)b * NT * NO + o0;

        ull wf[NH];
        #pragma unroll
        for (int kk = 0; kk < NH; kk++)
            wf[kk] = pack2(__ldg(W_fc + o0 * NH + kk), __ldg(W_fc + (o0+1) * NH + kk));
        const ull bfc = pack2(__ldg(b_fc + o0), __ldg(b_fc + o0 + 1));

        for (int e = 0; e <= NEP; e++){
            if (e > 0){
                #pragma unroll 4
                for (int u = 0; u < EP; u++){
                    const int t = (e - 1) * EP + u;
                    ull a0 = bfc, a1 = 0ull;
                    #pragma unroll
                    for (int kk = 0; kk < NH; kk++){
                        ull hd = hring[bw][t & (2*EP - 1)][kk];  // LDS.64 bcast
                        if (kk & 1) a1 = fma2(hd, wf[kk], a1);
                        else        a0 = fma2(hd, wf[kk], a0);
                    }
                    *reinterpret_cast<float2*>(ob + (size_t)t * NO) =
                        unpack2(add2(a0, a1));
                }
            }
            __syncthreads();
        }
    }
}

extern "C" void kernel_launch(void* const* d_in, const int* in_sizes, int n_in,
                              void* d_out, int out_size)
{
    (void)in_sizes; (void)n_in; (void)out_size;
    const float* x    = (const float*)d_in[0];
    const float* W_ih = (const float*)d_in[1];
    const float* W_hh = (const float*)d_in[2];
    const float* b_ih = (const float*)d_in[3];
    const float* b_hh = (const float*)d_in[4];
    const float* W_fc = (const float*)d_in[5];
    const float* b_fc = (const float*)d_in[6];
    float* out = (float*)d_out;

    prep_kernel<<<8, 256>>>(W_ih, b_ih, b_hh);
    gates_kernel<<<NM / 64, 128>>>(x);
    lstm_kernel<<<NB / 4, 256>>>(W_hh, W_fc, b_fc, out);
}

// round 15
// speedup vs baseline: 1.4420x; 1.4420x over previous
#include <cuda_runtime.h>

#define NB 256
#define NT 1024
#define NI 64
#define NH 25
#define NG 100    // real gate columns
#define NGP 104   // padded gate stride (13*8)
#define NO 64
#define NM (NB*NT)  // 262144 rows

// Precomputed input gates, layout [row][k*4+{i,f,g,o}] padded to 104: ~109 MB
static __device__ float g_gates[(size_t)NM * NGP];
// Precomputed W_ih fragments: [kstg 0..7][n 0..103][qid 0..3] = {bh0,bh1,bl0,bl1}
static __device__ uint4 g_wq[8 * NGP * 4];
static __device__ float g_bsum[NGP];

typedef unsigned long long ull;
typedef unsigned int uint;

__device__ __forceinline__ ull pack2(float a, float b){
    ull r; asm("mov.b64 %0,{%1,%2};" : "=l"(r) : "f"(a), "f"(b)); return r;
}
__device__ __forceinline__ float2 unpack2(ull v){
    float2 r; asm("mov.b64 {%0,%1},%2;" : "=f"(r.x), "=f"(r.y) : "l"(v)); return r;
}
__device__ __forceinline__ ull fma2(ull a, ull b, ull c){
    ull d; asm("fma.rn.f32x2 %0,%1,%2,%3;" : "=l"(d) : "l"(a), "l"(b), "l"(c)); return d;
}
__device__ __forceinline__ ull add2(ull a, ull b){
    ull d; asm("add.rn.f32x2 %0,%1,%2;" : "=l"(d) : "l"(a), "l"(b)); return d;
}
__device__ __forceinline__ float tanha(float x){
    float r; asm("tanh.approx.f32 %0,%1;" : "=f"(r) : "f"(x)); return r;
}
__device__ __forceinline__ float sig_t(float x){
    return fmaf(tanha(0.5f * x), 0.5f, 0.5f);
}
__device__ __forceinline__ unsigned smem_u32(const void* p){
    unsigned a;
    asm("{ .reg .u64 t; cvta.to.shared.u64 t, %1; cvt.u32.u64 %0, t; }"
        : "=r"(a) : "l"(p));
    return a;
}
__device__ __forceinline__ uint to_tf32(float v){
    uint r; asm("cvt.rna.tf32.f32 %0,%1;" : "=r"(r) : "f"(v)); return r;
}

#define MMA_TF32(c, a0,a1,a2,a3, b0,b1)                                   \
    asm volatile("mma.sync.aligned.m16n8k8.row.col.f32.tf32.tf32.f32 "    \
        "{%0,%1,%2,%3}, {%4,%5,%6,%7}, {%8,%9}, {%0,%1,%2,%3};"           \
        : "+f"((c)[0]), "+f"((c)[1]), "+f"((c)[2]), "+f"((c)[3])          \
        : "r"(a0), "r"(a1), "r"(a2), "r"(a3), "r"(b0), "r"(b1))

// ---------------------------------------------------------------------------
// Kernel 0: precompute W fragments + bias (R12 exact).
// ---------------------------------------------------------------------------
__global__ void prep_kernel(const float* __restrict__ W_ih,
                            const float* __restrict__ b_ih,
                            const float* __restrict__ b_hh)
{
    int tid = blockIdx.x * blockDim.x + threadIdx.x;
    const int total = 8 * NGP * 4;
    for (int i = tid; i < total; i += blockDim.x * gridDim.x){
        int qid  = i & 3;
        int n    = (i >> 2) % NGP;
        int kstg = i / (NGP * 4);
        int q = n & 3, kk = n >> 2;
        int k0 = kstg * 8 + qid, k1 = k0 + 4;
        float v0 = (kk < NH) ? W_ih[(q*NH + kk) * NI + k0] : 0.0f;
        float v1 = (kk < NH) ? W_ih[(q*NH + kk) * NI + k1] : 0.0f;
        uint h0 = to_tf32(v0), h1 = to_tf32(v1);
        uint l0 = to_tf32(v0 - __uint_as_float(h0));
        uint l1 = to_tf32(v1 - __uint_as_float(h1));
        g_wq[i] = make_uint4(h0, h1, l0, l1);
    }
    if (tid < NGP){
        int q = tid & 3, kk = tid >> 2;
        g_bsum[tid] = (kk < NH) ? (b_ih[q*NH + kk] + b_hh[q*NH + kk]) : 0.0f;
    }
}

// ---------------------------------------------------------------------------
// Kernel 1: gates via 3xTF32 tensor-core GEMM — 256-thread occupancy version.
// Same 64-row x 104-col tile, but 8 warps: warps 0-3 do n-tiles 0..6,
// warps 4-7 do n-tiles 7..12 (same A fragments, disjoint B tiles/stores).
// 2x warps/SM resident at the same 45KB smem -> better latency hiding;
// staging spread over 256 threads.
// ---------------------------------------------------------------------------
__global__ void __launch_bounds__(256) gates_kernel(const float* __restrict__ x)
{
    __shared__ uint  xs_hi[64][36], xs_lo[64][36];
    __shared__ uint4 bq[4][NGP][4];     // 1664 uint4 per pass

    const int tid  = threadIdx.x;
    const int lane = tid & 31;
    const int wid  = tid >> 5;          // 0..7
    const int wq   = wid & 3;           // row-quad (rows wq*16 .. wq*16+15)
    const int grp  = lane >> 2;         // 0..7
    const int qid  = lane & 3;          // 0..3
    const int nt0  = (wid < 4) ? 0 : 7; // n-tile base
    const int ntc  = (wid < 4) ? 7 : 6; // n-tile count
    const int rowbase = blockIdx.x * 64;

    float acc[7][4];
    #pragma unroll
    for (int i = 0; i < 7; i++)
        #pragma unroll
        for (int j = 0; j < 4; j++) acc[i][j] = 0.0f;

    const unsigned bq_s = smem_u32(&bq[0][0][0]);

    for (int pass = 0; pass < 2; pass++){
        const int ks = pass * 32;
        __syncthreads();

        {   // B fragments: 1664 x 16B chunks over 256 threads
            const char* src = reinterpret_cast<const char*>(g_wq)
                              + (size_t)pass * 4 * NGP * 4 * 16;
            #pragma unroll
            for (int i = 0; i < 7; i++){
                int ch = tid + i * 256;
                if (ch < 1664){
                    int off = ch * 16;
                    asm volatile("cp.async.ca.shared.global [%0], [%1], 16;"
                                 :: "r"(bq_s + off), "l"(src + off) : "memory");
                }
            }
            asm volatile("cp.async.commit_group;" ::: "memory");
        }

        // x tile: 64 rows x 32 cols = 512 float4 over 256 threads
        #pragma unroll
        for (int i = 0; i < 2; i++){
            int idx = tid + i * 256;
            int r = idx >> 3, f4 = idx & 7;
            float4 v = *reinterpret_cast<const float4*>(
                x + (size_t)(rowbase + r) * NI + ks + f4 * 4);
            uint4 hb, lb;
            hb.x = to_tf32(v.x); lb.x = to_tf32(v.x - __uint_as_float(hb.x));
            hb.y = to_tf32(v.y); lb.y = to_tf32(v.y - __uint_as_float(hb.y));
            hb.z = to_tf32(v.z); lb.z = to_tf32(v.z - __uint_as_float(hb.z));
            hb.w = to_tf32(v.w); lb.w = to_tf32(v.w - __uint_as_float(hb.w));
            *reinterpret_cast<uint4*>(&xs_hi[r][f4 * 4]) = hb;
            *reinterpret_cast<uint4*>(&xs_lo[r][f4 * 4]) = lb;
        }
        asm volatile("cp.async.wait_group 0;" ::: "memory");
        __syncthreads();

        #pragma unroll
        for (int kst = 0; kst < 4; kst++){
            const int r0 = wq * 16 + grp;
            const int c0 = kst * 8 + qid;
            uint ah0 = xs_hi[r0][c0],   ah1 = xs_hi[r0+8][c0];
            uint ah2 = xs_hi[r0][c0+4], ah3 = xs_hi[r0+8][c0+4];
            uint al0 = xs_lo[r0][c0],   al1 = xs_lo[r0+8][c0];
            uint al2 = xs_lo[r0][c0+4], al3 = xs_lo[r0+8][c0+4];
            #pragma unroll
            for (int i = 0; i < 7; i++){
                if (i < ntc){
                    int nt = nt0 + i;
                    uint4 bv = bq[kst][nt * 8 + grp][qid];
                    MMA_TF32(acc[i], ah0, ah1, ah2, ah3, bv.x, bv.y);
                    MMA_TF32(acc[i], al0, al1, al2, al3, bv.x, bv.y);
                    MMA_TF32(acc[i], ah0, ah1, ah2, ah3, bv.z, bv.w);
                }
            }
        }
    }

    // epilogue: bias + store (float2, 32B-aligned per 4-lane group)
    const size_t rg = (size_t)(rowbase + wq * 16 + grp);
    #pragma unroll
    for (int i = 0; i < 7; i++){
        if (i < ntc){
            int nt = nt0 + i;
            int col = nt * 8 + 2 * qid;
            float2 bsv = *reinterpret_cast<const float2*>(&g_bsum[col]);
            float2 v0 = { acc[i][0] + bsv.x, acc[i][1] + bsv.y };
            float2 v1 = { acc[i][2] + bsv.x, acc[i][3] + bsv.y };
            *reinterpret_cast<float2*>(&g_gates[ rg      * NGP + col]) = v0;
            *reinterpret_cast<float2*>(&g_gates[(rg + 8) * NGP + col]) = v1;
        }
    }
}

// ---------------------------------------------------------------------------
// Kernel 2: LSTM scan with helper-warp FC offload (R12 exact, proven).
// Block = 128 threads: warps 0,1 = scan (batches 2bx, 2bx+1) on SMSP 0,1;
// warps 2,3 = FC helpers on SMSP 2,3. h via 32-slot smem ring, 16-step
// epochs, one __syncthreads per epoch half.
// ---------------------------------------------------------------------------
#define RD   16   // gx ring slots
#define RPD  12   // gx prefetch distance
#define EP   16   // steps per epoch
#define NEP  (NT/EP)   // 64 epochs

__global__ void __launch_bounds__(128, 1) lstm_kernel(
    const float* __restrict__ W_hh, const float* __restrict__ W_fc,
    const float* __restrict__ b_fc, float* __restrict__ out)
{
    __shared__ ull ring[2][RD][32][2];    // gx cp.async ring per scan warp
    __shared__ ull hring[2][2*EP][32];    // duplicated h pairs [batch][slot][lane]

    const int tid  = threadIdx.x;
    const int lane = tid & 31;
    const int wrp  = tid >> 5;            // 0..3
    const int bw   = wrp & 1;             // batch slot within block
    const int b    = blockIdx.x * 2 + bw;
    const bool is_scan = (wrp < 2);

    if (is_scan){
        // ------------------- producer: LSTM recurrence -------------------
        const int k = (lane < NH) ? lane : NH - 1;
        const float* gx = g_gates + (size_t)b * NT * NGP + 4 * k;

        ull w_if[NH], w_go[NH];
        #pragma unroll
        for (int kk = 0; kk < NH; kk++){
            w_if[kk] = pack2(__ldg(W_hh + (     k) * NH + kk), __ldg(W_hh + (NH  + k) * NH + kk));
            w_go[kk] = pack2(__ldg(W_hh + (2*NH+k) * NH + kk), __ldg(W_hh + (3*NH+k) * NH + kk));
        }

        const unsigned rbase = smem_u32(&ring[bw][0][lane][0]);
        #define SLOT_ADDR(s) (rbase + (unsigned)(s) * (32u * 16u))

        #pragma unroll
        for (int d = 0; d < RPD; d++){
            asm volatile("cp.async.ca.shared.global [%0], [%1], 16;"
                         :: "r"(SLOT_ADDR(d)), "l"(gx + (size_t)d * NGP) : "memory");
            asm volatile("cp.async.commit_group;" ::: "memory");
        }

        float h = 0.0f, c = 0.0f;

        for (int e = 0; e <= NEP; e++){
            if (e < NEP){
                #pragma unroll 4
                for (int u = 0; u < EP; u++){
                    const int t = e * EP + u;
                    asm volatile("cp.async.wait_group 11;" ::: "memory");
                    float4 pv = *reinterpret_cast<const float4*>(
                                    &ring[bw][t & (RD-1)][lane][0]);

                    {   // refill slot t+RPD
                        unsigned pred = (t + RPD < NT) ? 1u : 0u;
                        asm volatile(
                            "{ .reg .pred q; setp.ne.u32 q, %0, 0;"
                            "  @q cp.async.ca.shared.global [%1], [%2], 16; }"
                            :: "r"(pred), "r"(SLOT_ADDR((t + RPD) & (RD-1))),
                               "l"(gx + (size_t)(t + RPD) * NGP) : "memory");
                        asm volatile("cp.async.commit_group;" ::: "memory");
                    }

                    ull aif[4], ago[4];
                    aif[0] = pack2(pv.x, pv.y); aif[1] = 0ull; aif[2] = 0ull; aif[3] = 0ull;
                    ago[0] = pack2(pv.z, pv.w); ago[1] = 0ull; ago[2] = 0ull; ago[3] = 0ull;

                    #pragma unroll
                    for (int kk = 0; kk < NH; kk++){
                        float hv = __shfl_sync(0xffffffffu, h, kk);
                        ull hd = pack2(hv, hv);
                        aif[kk & 3] = fma2(hd, w_if[kk], aif[kk & 3]);
                        ago[kk & 3] = fma2(hd, w_go[kk], ago[kk & 3]);
                    }

                    float2 gif = unpack2(add2(add2(aif[0], aif[1]), add2(aif[2], aif[3])));
                    float2 ggo = unpack2(add2(add2(ago[0], ago[1]), add2(ago[2], ago[3])));
                    float iv = sig_t(gif.x);
                    float fv = sig_t(gif.y);
                    float gv = tanha(ggo.x);
                    float ov = sig_t(ggo.y);
                    c = fv * c + iv * gv;
                    h = ov * tanha(c);

                    hring[bw][t & (2*EP - 1)][lane] = pack2(h, h);
                }
            }
            __syncthreads();   // publish epoch e half; helpers drained e-1
        }
        #undef SLOT_ADDR
    } else {
        // ------------------- consumer: FC head -------------------
        const int o0 = 2 * lane;
        float* ob = out + (size_t)b * NT * NO + o0;

        ull wf[NH];
        #pragma unroll
        for (int kk = 0; kk < NH; kk++)
            wf[kk] = pack2(__ldg(W_fc + o0 * NH + kk), __ldg(W_fc + (o0+1) * NH + kk));
        const ull bfc = pack2(__ldg(b_fc + o0), __ldg(b_fc + o0 + 1));

        for (int e = 0; e <= NEP; e++){
            if (e > 0){
                #pragma unroll 4
                for (int u = 0; u < EP; u++){
                    const int t = (e - 1) * EP + u;
                    ull a0 = bfc, a1 = 0ull;
                    #pragma unroll
                    for (int kk = 0; kk < NH; kk++){
                        ull hd = hring[bw][t & (2*EP - 1)][kk];  // LDS.64 bcast
                        if (kk & 1) a1 = fma2(hd, wf[kk], a1);
                        else        a0 = fma2(hd, wf[kk], a0);
                    }
                    *reinterpret_cast<float2*>(ob + (size_t)t * NO) =
                        unpack2(add2(a0, a1));
                }
            }
            __syncthreads();
        }
    }
}

extern "C" void kernel_launch(void* const* d_in, const int* in_sizes, int n_in,
                              void* d_out, int out_size)
{
    (void)in_sizes; (void)n_in; (void)out_size;
    const float* x    = (const float*)d_in[0];
    const float* W_ih = (const float*)d_in[1];
    const float* W_hh = (const float*)d_in[2];
    const float* b_ih = (const float*)d_in[3];
    const float* b_hh = (const float*)d_in[4];
    const float* W_fc = (const float*)d_in[5];
    const float* b_fc = (const float*)d_in[6];
    float* out = (float*)d_out;

    prep_kernel<<<8, 256>>>(W_ih, b_ih, b_hh);
    gates_kernel<<<NM / 64, 256>>>(x);
    lstm_kernel<<<NB / 2, 128>>>(W_hh, W_fc, b_fc, out);
}

// round 17
// speedup vs baseline: 1.5530x; 1.0770x over previous
#include <cuda_runtime.h>

#define NB 256
#define NT 1024
#define NI 64
#define NH 25
#define NG 100    // real gate columns
#define NGP 104   // padded gate stride (13*8)
#define NO 64
#define NM (NB*NT)    // 262144 rows
#define NCH 64        // t-chunks of 16 timesteps (64 tiles each)
#define NTILE 4096    // gates tiles: t (1024) x batch-quarter (4)
#define NSCAN 64      // scan blocks
#define NGATE 84      // persistent gates blocks
#define TSTR ((size_t)NB * NGP)   // floats per timestep in t-major g_gates

// Input gates, T-MAJOR: g_gates[(t*NB + b)*NGP + 4k + q] : ~109 MB
static __device__ float g_gates[(size_t)NM * NGP];
// Precomputed W_ih fragments: [kstg 0..7][n 0..103][qid 0..3]
static __device__ uint4 g_wq[8 * NGP * 4];
static __device__ float g_bsum[NGP];
// Per-chunk completion counters
static __device__ int   g_cnt[NCH];

typedef unsigned long long ull;
typedef unsigned int uint;

__device__ __forceinline__ ull pack2(float a, float b){
    ull r; asm("mov.b64 %0,{%1,%2};" : "=l"(r) : "f"(a), "f"(b)); return r;
}
__device__ __forceinline__ float2 unpack2(ull v){
    float2 r; asm("mov.b64 {%0,%1},%2;" : "=f"(r.x), "=f"(r.y) : "l"(v)); return r;
}
__device__ __forceinline__ ull fma2(ull a, ull b, ull c){
    ull d; asm("fma.rn.f32x2 %0,%1,%2,%3;" : "=l"(d) : "l"(a), "l"(b), "l"(c)); return d;
}
__device__ __forceinline__ ull add2(ull a, ull b){
    ull d; asm("add.rn.f32x2 %0,%1,%2;" : "=l"(d) : "l"(a), "l"(b)); return d;
}
__device__ __forceinline__ float tanha(float x){
    float r; asm("tanh.approx.f32 %0,%1;" : "=f"(r) : "f"(x)); return r;
}
__device__ __forceinline__ float sig_t(float x){
    return fmaf(tanha(0.5f * x), 0.5f, 0.5f);
}
__device__ __forceinline__ unsigned smem_u32(const void* p){
    unsigned a;
    asm("{ .reg .u64 t; cvta.to.shared.u64 t, %1; cvt.u32.u64 %0, t; }"
        : "=r"(a) : "l"(p));
    return a;
}
__device__ __forceinline__ uint to_tf32(float v){
    uint r; asm("cvt.rna.tf32.f32 %0,%1;" : "=r"(r) : "f"(v)); return r;
}
__device__ __forceinline__ void wait_chunk(int c){
    const int* p = &g_cnt[c];
    int v;
    for (;;){
        asm volatile("ld.acquire.gpu.b32 %0,[%1];" : "=r"(v) : "l"(p) : "memory");
        if (v >= 64) break;
        __nanosleep(200);
    }
}

#define MMA_TF32(c, a0,a1,a2,a3, b0,b1)                                   \
    asm volatile("mma.sync.aligned.m16n8k8.row.col.f32.tf32.tf32.f32 "    \
        "{%0,%1,%2,%3}, {%4,%5,%6,%7}, {%8,%9}, {%0,%1,%2,%3};"           \
        : "+f"((c)[0]), "+f"((c)[1]), "+f"((c)[2]), "+f"((c)[3])          \
        : "r"(a0), "r"(a1), "r"(a2), "r"(a3), "r"(b0), "r"(b1))

// ---------------------------------------------------------------------------
// Kernel 0: precompute W fragments + bias; reset chunk counters.
// ---------------------------------------------------------------------------
__global__ void prep_kernel(const float* __restrict__ W_ih,
                            const float* __restrict__ b_ih,
                            const float* __restrict__ b_hh)
{
    int tid = blockIdx.x * blockDim.x + threadIdx.x;
    const int total = 8 * NGP * 4;
    for (int i = tid; i < total; i += blockDim.x * gridDim.x){
        int qid  = i & 3;
        int n    = (i >> 2) % NGP;
        int kstg = i / (NGP * 4);
        int q = n & 3, kk = n >> 2;
        int k0 = kstg * 8 + qid, k1 = k0 + 4;
        float v0 = (kk < NH) ? W_ih[(q*NH + kk) * NI + k0] : 0.0f;
        float v1 = (kk < NH) ? W_ih[(q*NH + kk) * NI + k1] : 0.0f;
        uint h0 = to_tf32(v0), h1 = to_tf32(v1);
        uint l0 = to_tf32(v0 - __uint_as_float(h0));
        uint l1 = to_tf32(v1 - __uint_as_float(h1));
        g_wq[i] = make_uint4(h0, h1, l0, l1);
    }
    if (tid < NGP){
        int q = tid & 3, kk = tid >> 2;
        g_bsum[tid] = (kk < NH) ? (b_ih[q*NH + kk] + b_hh[q*NH + kk]) : 0.0f;
    }
    if (tid < NCH) g_cnt[tid] = 0;
}

// ---------------------------------------------------------------------------
// Gates worker (persistent): loops tiles g = (bid-NSCAN) + i*NGATE.
// B fragments (both passes) loaded ONCE; x raw-prefetched one tile ahead.
// dsm layout: bq[8][NGP][4] (53248B) | xs_hi[64][68] | xs_lo[64][68] | raw 16KB
// ---------------------------------------------------------------------------
#define RDs   16
#define RPDs  12
#define EPs   16
#define NEPs  (NT/EPs)
#define SMEM_FUSED (120*1024)

__device__ void gates_worker(const float* __restrict__ x, char* dsm)
{
    uint4 (*bq)[NGP][4] = reinterpret_cast<uint4(*)[NGP][4]>(dsm);
    uint  (*xsh)[68]    = reinterpret_cast<uint(*)[68]>(dsm + 53248);
    uint  (*xsl)[68]    = reinterpret_cast<uint(*)[68]>(dsm + 70656);
    float4* raw         = reinterpret_cast<float4*>(dsm + 88064);  // 1024 f4

    const int tid  = threadIdx.x;
    const int lane = tid & 31;
    const int wid  = tid >> 5;          // 0..7
    const int wq   = wid & 3;
    const int grp  = lane >> 2;
    const int qid  = lane & 3;
    const int nt0  = (wid < 4) ? 0 : 7;
    const int ntc  = (wid < 4) ? 7 : 6;
    const int gbid = blockIdx.x - NSCAN;

    const unsigned bq_s  = smem_u32(&bq[0][0][0]);
    const unsigned raw_s = smem_u32(raw);

    // ---- load B fragments once (3328 x 16B) ----
    {
        const char* src = reinterpret_cast<const char*>(g_wq);
        #pragma unroll
        for (int i = 0; i < 13; i++){
            int ch = tid + i * 256;
            if (ch < 3328){
                int off = ch * 16;
                asm volatile("cp.async.ca.shared.global [%0], [%1], 16;"
                             :: "r"(bq_s + off), "l"(src + off) : "memory");
            }
        }
    }
    // ---- prefetch raw x for first tile ----
    {
        int g = gbid;
        int t = g >> 2, b0 = (g & 3) * 64;
        #pragma unroll
        for (int i = 0; i < 4; i++){
            int idx = tid + i * 256;       // 0..1023
            int r = idx >> 4, c4 = idx & 15;
            const float* src = x + ((size_t)(b0 + r) * NT + t) * NI + c4 * 4;
            asm volatile("cp.async.ca.shared.global [%0], [%1], 16;"
                         :: "r"(raw_s + idx * 16), "l"(src) : "memory");
        }
        asm volatile("cp.async.commit_group;" ::: "memory");
    }

    for (int g = gbid; g < NTILE; g += NGATE){
        const int t  = g >> 2;
        const int b0 = (g & 3) * 64;

        asm volatile("cp.async.wait_group 0;" ::: "memory");
        __syncthreads();

        // cvt raw -> hi/lo split
        #pragma unroll
        for (int i = 0; i < 4; i++){
            int idx = tid + i * 256;
            int r = idx >> 4, c4 = idx & 15;
            float4 v = raw[idx];
            uint4 hb, lb;
            hb.x = to_tf32(v.x); lb.x = to_tf32(v.x - __uint_as_float(hb.x));
            hb.y = to_tf32(v.y); lb.y = to_tf32(v.y - __uint_as_float(hb.y));
            hb.z = to_tf32(v.z); lb.z = to_tf32(v.z - __uint_as_float(hb.z));
            hb.w = to_tf32(v.w); lb.w = to_tf32(v.w - __uint_as_float(hb.w));
            *reinterpret_cast<uint4*>(&xsh[r][c4 * 4]) = hb;
            *reinterpret_cast<uint4*>(&xsl[r][c4 * 4]) = lb;
        }
        __syncthreads();   // raw consumed; safe to overwrite

        // prefetch raw for tile g+NGATE
        {
            int gn = g + NGATE;
            if (gn < NTILE){
                int tn = gn >> 2, bn = (gn & 3) * 64;
                #pragma unroll
                for (int i = 0; i < 4; i++){
                    int idx = tid + i * 256;
                    int r = idx >> 4, c4 = idx & 15;
                    const float* src = x + ((size_t)(bn + r) * NT + tn) * NI + c4 * 4;
                    asm volatile("cp.async.ca.shared.global [%0], [%1], 16;"
                                 :: "r"(raw_s + idx * 16), "l"(src) : "memory");
                }
            }
            asm volatile("cp.async.commit_group;" ::: "memory");
        }

        // MMA mainloop
        float acc[7][4];
        #pragma unroll
        for (int i = 0; i < 7; i++)
            #pragma unroll
            for (int j = 0; j < 4; j++) acc[i][j] = 0.0f;

        #pragma unroll
        for (int kstg = 0; kstg < 8; kstg++){
            const int r0 = wq * 16 + grp;
            const int c0 = kstg * 8 + qid;
            uint ah0 = xsh[r0][c0],   ah1 = xsh[r0+8][c0];
            uint ah2 = xsh[r0][c0+4], ah3 = xsh[r0+8][c0+4];
            uint al0 = xsl[r0][c0],   al1 = xsl[r0+8][c0];
            uint al2 = xsl[r0][c0+4], al3 = xsl[r0+8][c0+4];
            #pragma unroll
            for (int i = 0; i < 7; i++){
                if (i < ntc){
                    int nt = nt0 + i;
                    uint4 bv = bq[kstg][nt * 8 + grp][qid];
                    MMA_TF32(acc[i], ah0, ah1, ah2, ah3, bv.x, bv.y);
                    MMA_TF32(acc[i], al0, al1, al2, al3, bv.x, bv.y);
                    MMA_TF32(acc[i], ah0, ah1, ah2, ah3, bv.z, bv.w);
                }
            }
        }

        // epilogue: bias + t-major store
        const size_t rg = (size_t)t * NB + b0 + wq * 16 + grp;
        #pragma unroll
        for (int i = 0; i < 7; i++){
            if (i < ntc){
                int nt = nt0 + i;
                int col = nt * 8 + 2 * qid;
                float2 bsv = *reinterpret_cast<const float2*>(&g_bsum[col]);
                float2 v0 = { acc[i][0] + bsv.x, acc[i][1] + bsv.y };
                float2 v1 = { acc[i][2] + bsv.x, acc[i][3] + bsv.y };
                *reinterpret_cast<float2*>(&g_gates[ rg      * NGP + col]) = v0;
                *reinterpret_cast<float2*>(&g_gates[(rg + 8) * NGP + col]) = v1;
            }
        }

        __threadfence();
        __syncthreads();
        if (tid == 0){
            asm volatile("fence.acq_rel.gpu;" ::: "memory");
            atomicAdd(&g_cnt[g >> 6], 1);
        }
    }
}

// ---------------------------------------------------------------------------
// Scan worker: R16 per-warp LSTM + fused FC; reads t-major g_gates gated by
// chunk counters. 4 warps = 4 batches; threads 128..255 exit (no block sync).
// ---------------------------------------------------------------------------
__device__ void scan_worker(const float* __restrict__ W_hh,
                            const float* __restrict__ W_fc,
                            const float* __restrict__ b_fc,
                            float* __restrict__ out, char* dsm)
{
    const int lane = threadIdx.x & 31;
    const int wrp  = threadIdx.x >> 5;     // 0..3 (callers guarantee <4)
    const int b    = blockIdx.x * 4 + wrp;
    const int k    = (lane < NH) ? lane : NH - 1;
    const int o0   = 2 * lane;

    const float* gx = g_gates + (size_t)b * NGP + 4 * k;   // + t*TSTR per step
    float*       ob = out     + (size_t)b * NT * NO + o0;

    ull w_if[NH], w_go[NH], wf[NH];
    #pragma unroll
    for (int kk = 0; kk < NH; kk++){
        w_if[kk] = pack2(__ldg(W_hh + (     k) * NH + kk), __ldg(W_hh + (NH  + k) * NH + kk));
        w_go[kk] = pack2(__ldg(W_hh + (2*NH+k) * NH + kk), __ldg(W_hh + (3*NH+k) * NH + kk));
        wf[kk]   = pack2(__ldg(W_fc + o0 * NH + kk),       __ldg(W_fc + (o0+1) * NH + kk));
    }
    const ull bfc = pack2(__ldg(b_fc + o0), __ldg(b_fc + o0 + 1));

    char* ringw = dsm + (size_t)wrp * RDs * 32 * 16;
    const unsigned rbase = smem_u32(ringw) + (unsigned)lane * 16u;
    #define SLOT_ADDR(s) (rbase + (unsigned)(s) * (32u * 16u))
    #define SLOT_PTR(s)  (ringw + (size_t)(s) * (32 * 16) + lane * 16)

    wait_chunk(0);   // t 0..15 ready before prologue prefetch (t<=11)

    #pragma unroll
    for (int d = 0; d < RPDs; d++){
        asm volatile("cp.async.ca.shared.global [%0], [%1], 16;"
                     :: "r"(SLOT_ADDR(d)), "l"(gx + (size_t)d * TSTR) : "memory");
        asm volatile("cp.async.commit_group;" ::: "memory");
    }

    float h = 0.0f, c = 0.0f;

    for (int e = 0; e < NEPs; e++){
        {   // epoch e prefetches reach t = 16e+27 -> need chunk e+1
            int ch = e + 1; if (ch > NCH - 1) ch = NCH - 1;
            wait_chunk(ch);
        }
        #pragma unroll 4
        for (int u = 0; u < EPs; u++){
            const int t = e * EPs + u;
            asm volatile("cp.async.wait_group 11;" ::: "memory");
            float4 pv = *reinterpret_cast<const float4*>(SLOT_PTR(t & (RDs-1)));

            {   // refill slot t+RPDs
                unsigned pred = (t + RPDs < NT) ? 1u : 0u;
                asm volatile(
                    "{ .reg .pred q; setp.ne.u32 q, %0, 0;"
                    "  @q cp.async.ca.shared.global [%1], [%2], 16; }"
                    :: "r"(pred), "r"(SLOT_ADDR((t + RPDs) & (RDs-1))),
                       "l"(gx + (size_t)(t + RPDs) * TSTR) : "memory");
                asm volatile("cp.async.commit_group;" ::: "memory");
            }

            ull aif[4], ago[4], afc[2];
            aif[0] = pack2(pv.x, pv.y); aif[1] = 0ull; aif[2] = 0ull; aif[3] = 0ull;
            ago[0] = pack2(pv.z, pv.w); ago[1] = 0ull; ago[2] = 0ull; ago[3] = 0ull;
            afc[0] = bfc;               afc[1] = 0ull;

            #pragma unroll
            for (int kk = 0; kk < NH; kk++){
                float hv = __shfl_sync(0xffffffffu, h, kk);
                ull hd = pack2(hv, hv);
                aif[kk & 3] = fma2(hd, w_if[kk], aif[kk & 3]);
                ago[kk & 3] = fma2(hd, w_go[kk], ago[kk & 3]);
                afc[kk & 1] = fma2(hd, wf[kk],   afc[kk & 1]);
            }
            if (t > 0)
                *reinterpret_cast<float2*>(ob + (size_t)(t - 1) * NO) =
                    unpack2(add2(afc[0], afc[1]));

            float2 gif = unpack2(add2(add2(aif[0], aif[1]), add2(aif[2], aif[3])));
            float2 ggo = unpack2(add2(add2(ago[0], ago[1]), add2(ago[2], ago[3])));
            float iv = sig_t(gif.x);
            float fv = sig_t(gif.y);
            float gv = tanha(ggo.x);
            float ov = sig_t(ggo.y);
            c = fv * c + iv * gv;
            h = ov * tanha(c);
        }
    }
    {   // final FC for h_{T-1}
        ull a0 = bfc, a1 = 0ull;
        #pragma unroll
        for (int kk = 0; kk < NH; kk++){
            float hv = __shfl_sync(0xffffffffu, h, kk);
            ull hd = pack2(hv, hv);
            if (kk & 1) a1 = fma2(hd, wf[kk], a1);
            else        a0 = fma2(hd, wf[kk], a0);
        }
        *reinterpret_cast<float2*>(ob + (size_t)(NT - 1) * NO) = unpack2(add2(a0, a1));
    }
    #undef SLOT_ADDR
    #undef SLOT_PTR
}

// ---------------------------------------------------------------------------
// Fused kernel: 148 blocks x 256 thr, 120KB dsm -> exactly 1 block/SM, all
// resident in wave 1 (no deadlock). Blocks 0..63 scan, 64..147 gates workers.
// ---------------------------------------------------------------------------
__global__ void __launch_bounds__(256, 1) fused_kernel(
    const float* __restrict__ x,
    const float* __restrict__ W_hh, const float* __restrict__ W_fc,
    const float* __restrict__ b_fc, float* __restrict__ out)
{
    extern __shared__ char dsm[];
    if (blockIdx.x < NSCAN){
        if (threadIdx.x < 128)            // no block-wide sync in scan path
            scan_worker(W_hh, W_fc, b_fc, out, dsm);
        return;
    }
    gates_worker(x, dsm);
}

extern "C" void kernel_launch(void* const* d_in, const int* in_sizes, int n_in,
                              void* d_out, int out_size)
{
    (void)in_sizes; (void)n_in; (void)out_size;
    const float* x    = (const float*)d_in[0];
    const float* W_ih = (const float*)d_in[1];
    const float* W_hh = (const float*)d_in[2];
    const float* b_ih = (const float*)d_in[3];
    const float* b_hh = (const float*)d_in[4];
    const float* W_fc = (const float*)d_in[5];
    const float* b_fc = (const float*)d_in[6];
    float* out = (float*)d_out;

    cudaFuncSetAttribute(fused_kernel,
                         cudaFuncAttributeMaxDynamicSharedMemorySize, SMEM_FUSED);

    prep_kernel<<<8, 256>>>(W_ih, b_ih, b_hh);
    fused_kernel<<<NSCAN + NGATE, 256, SMEM_FUSED>>>(x, W_hh, W_fc, b_fc, out);
}